// round 17
// baseline (speedup 1.0000x reference)
#include <cuda_runtime.h>
#include <cuda_fp16.h>
#include <cstdint>
#include <cstddef>

#define N_NODES     100000
#define N_PAD       100096            /* 782 * 128 */
#define DIM         256
#define N_ET        6
#define M_PER_TYPE  400000
#define TOTAL_EDGES (N_ET * M_PER_TYPE)
#define PAD_EDGES   (TOTAL_EDGES + 7 * N_NODES + 8)   /* padded-seg worst case */
#define NBIG        (N_ET * DIM)      /* 1536 */
#define POS_TAB     512
#define SCAN_BLK    1024
#define N_SBLK      ((N_NODES + SCAN_BLK - 1) / SCAN_BLK)   /* 98 */
#define CNT_PAD     (N_SBLK * SCAN_BLK)
#define DUMMY_REC   (((uint32_t)N_NODES) << 12)       /* zero prop row, pos 0 */

// ---------------- device scratch (sanctioned: __device__ globals) ----------
// +1 row on g_proph: the dummy row, never written -> stays zero (module init)
__device__ __half   g_proph[(size_t)(N_NODES + 1) * NBIG];
__device__ __half   g_gatingh[POS_TAB * DIM];
__device__ int      g_cnt[CNT_PAD];
__device__ int      g_off[N_NODES + 1];               // PADDED CSR offsets
__device__ int      g_cur[N_NODES];
__device__ int      g_bsum[N_SBLK + 1];
__device__ uint32_t g_sorted[PAD_EDGES];
__device__ __half   g_Ah[(size_t)N_PAD * DIM];
__device__ __half   g_Wh[NBIG * DIM];

// ---------------- fused fp16 convert pass ------------------------------------
__global__ void convert_kernel(const float* __restrict__ A,
                               const float* __restrict__ W) {
    int i = blockIdx.x * blockDim.x + threadIdx.x;
    const int nA = N_NODES * DIM;
    if (i < nA) {
        g_Ah[i] = __float2half_rn(A[i]);
    } else {
        int j = i - nA;
        if (j < NBIG * DIM) g_Wh[j] = __float2half_rn(W[j]);
    }
}

// ---------------- gating + zero counters ------------------------------------
__global__ void gating_kernel(const float* __restrict__ Wp,
                              const float* __restrict__ bp) {
    __shared__ float emb[DIM];
    const int p = blockIdx.x;
    const int t = threadIdx.x;
    if (t < 127) {
        float y    = (float)(2 * t) / 254.0f;
        float invf = 1.0f / powf(10000.0f, y);
        float ang  = (float)p * invf;
        emb[t]       = sinf(ang);
        emb[t + 127] = cosf(ang);
    } else if (t >= 254) {
        emb[t] = 0.0f;
    }
    int bi = blockIdx.x * blockDim.x + t;
    if (bi < CNT_PAD) g_cnt[bi] = 0;
    __syncthreads();

    float s = bp[t];
    const float* w = Wp + (size_t)t * DIM;
#pragma unroll 8
    for (int k = 0; k < DIM; ++k) s += emb[k] * w[k];
    g_gatingh[p * DIM + t] = __float2half_rn(2.0f / (1.0f + expf(-s)));
}

// ---------------- counting sort (padded-to-8 segments) -----------------------
__global__ void hist_kernel(const int* __restrict__ edges) {
    int e = blockIdx.x * blockDim.x + threadIdx.x;
    if (e >= TOTAL_EDGES) return;
    atomicAdd(&g_cnt[edges[(size_t)2 * e + 1]], 1);
}

__global__ void scan1_kernel() {
    __shared__ int sh[SCAN_BLK];
    int t   = threadIdx.x;
    int idx = blockIdx.x * SCAN_BLK + t;
    int v   = (idx < N_NODES) ? ((g_cnt[idx] + 7) & ~7) : 0;   // round8
    sh[t] = v;
    __syncthreads();
#pragma unroll
    for (int off = 1; off < SCAN_BLK; off <<= 1) {
        int x = (t >= off) ? sh[t - off] : 0;
        __syncthreads();
        sh[t] += x;
        __syncthreads();
    }
    if (idx < N_NODES) g_off[idx] = sh[t] - v;
    if (t == SCAN_BLK - 1) g_bsum[blockIdx.x] = sh[t];
}

__global__ void scan2_kernel() {
    __shared__ int sh[128];
    int t = threadIdx.x;
    int v = (t < N_SBLK) ? g_bsum[t] : 0;
    sh[t] = v;
    __syncthreads();
#pragma unroll
    for (int off = 1; off < 128; off <<= 1) {
        int x = (t >= off) ? sh[t - off] : 0;
        __syncthreads();
        sh[t] += x;
        __syncthreads();
    }
    if (t < N_SBLK) g_bsum[t] = sh[t] - v;
    if (t == 127) g_off[N_NODES] = sh[127];
}

__global__ void scan3_kernel() {
    int idx = blockIdx.x * SCAN_BLK + threadIdx.x;
    if (idx >= N_NODES) return;
    int o = g_off[idx] + g_bsum[blockIdx.x];
    g_off[idx] = o;
    g_cur[idx] = o;
}

__global__ void place_kernel(const int* __restrict__ edges,
                             const int* __restrict__ posl) {
    int e = blockIdx.x * blockDim.x + threadIdx.x;
    if (e >= TOTAL_EDGES) return;
    int src  = edges[(size_t)2 * e];
    int tgt  = edges[(size_t)2 * e + 1];
    int pos  = posl[e];
    int type = e / M_PER_TYPE;
    int p = atomicAdd(&g_cur[tgt], 1);
    g_sorted[p] = ((uint32_t)src << 12) | ((uint32_t)type << 9) | (uint32_t)pos;
}

// fill padded slots with the zero-row dummy record
__global__ void fill_kernel() {
    int t = blockIdx.x * blockDim.x + threadIdx.x;
    if (t >= N_NODES) return;
    int e   = g_cur[t];           // = seg start + true count (post-place)
    int end = g_off[t + 1];
    for (; e < end; ++e) g_sorted[e] = DUMMY_REC;
}

// ---------------- GEMM: fp16 mma + ldmatrix, cp.async double-buffered -------
#define OFF_AH 0
#define OFF_BH 5120
#define BUF_HALVES 10240
#define SMEM_GEMM_BYTES (2 * BUF_HALVES * 2)   /* 40960 */

__device__ __forceinline__ uint32_t smem_u32(const void* p) {
    uint32_t a;
    asm("{ .reg .u64 t; cvta.to.shared.u64 t, %1; cvt.u32.u64 %0, t; }"
        : "=r"(a) : "l"(p));
    return a;
}
__device__ __forceinline__ void cp16(uint32_t dst, const void* src) {
    asm volatile("cp.async.ca.shared.global [%0], [%1], 16;"
                 :: "r"(dst), "l"(src));
}
__device__ __forceinline__ void cp_commit() {
    asm volatile("cp.async.commit_group;" ::: "memory");
}
template <int N>
__device__ __forceinline__ void cp_wait() {
    asm volatile("cp.async.wait_group %0;" :: "n"(N) : "memory");
}
__device__ __forceinline__ void ldsm4(uint32_t& r0, uint32_t& r1,
                                      uint32_t& r2, uint32_t& r3, uint32_t addr) {
    asm volatile("ldmatrix.sync.aligned.m8n8.x4.shared.b16 {%0,%1,%2,%3}, [%4];"
                 : "=r"(r0), "=r"(r1), "=r"(r2), "=r"(r3) : "r"(addr));
}
__device__ __forceinline__ void mmah16(float* d, const uint32_t* a, const uint32_t* b) {
    asm volatile(
        "mma.sync.aligned.m16n8k16.row.col.f32.f16.f16.f32 "
        "{%0,%1,%2,%3}, {%4,%5,%6,%7}, {%8,%9}, {%0,%1,%2,%3};"
        : "+f"(d[0]), "+f"(d[1]), "+f"(d[2]), "+f"(d[3])
        : "r"(a[0]), "r"(a[1]), "r"(a[2]), "r"(a[3]), "r"(b[0]), "r"(b[1]));
}

__global__ __launch_bounds__(256, 2)
void gemm_kernel(const float* __restrict__ bias) {
    extern __shared__ __half sm[];
    const uint32_t sb = smem_u32(sm);
    const int tid  = threadIdx.x;
    const int lane = tid & 31;
    const int wid  = tid >> 5;
    const int wm   = (wid & 3) * 32;
    const int wn   = (wid >> 2) * 64;
    const int mBase = blockIdx.y * 128;
    const int nBase = blockIdx.x * 128;

    const int g = lane >> 3;
    const int i = lane & 7;
    const int a_row_off = (wm + i + ((g & 1) << 3)) * 40 + ((g >> 1) << 3);
    const int b_col_off = ((g & 1) << 3);
    const int b_row_i   = wn + ((g >> 1) << 3) + i;

    auto stage = [&](int buf, int kc) {
        uint32_t base = sb + buf * (BUF_HALVES * 2);
#pragma unroll
        for (int t4 = 0; t4 < 4; t4++) {
            int t = tid + t4 * 256;
            if (t < 512) {
                int r = t >> 2, c = t & 3;
                cp16(base + (OFF_AH + r * 40) * 2 + c * 16,
                     g_Ah + (size_t)(mBase + r) * DIM + kc * 32 + c * 8);
            } else {
                int idx = t - 512, r = idx >> 2, c = idx & 3;
                cp16(base + (OFF_BH + r * 40) * 2 + c * 16,
                     g_Wh + (size_t)(nBase + r) * DIM + kc * 32 + c * 8);
            }
        }
    };

    float acc[2][8][4];
#pragma unroll
    for (int x = 0; x < 2; x++)
#pragma unroll
        for (int j = 0; j < 8; j++)
#pragma unroll
            for (int k = 0; k < 4; k++) acc[x][j][k] = 0.f;

    stage(0, 0);
    cp_commit();

    int buf = 0;
    for (int kc = 0; kc < 8; kc++) {
        if (kc < 7) {
            stage(buf ^ 1, kc + 1);
            cp_commit();
            cp_wait<1>();
        } else {
            cp_wait<0>();
        }
        __syncthreads();

        const uint32_t base = sb + buf * (BUF_HALVES * 2);

#pragma unroll
        for (int kk = 0; kk < 32; kk += 16) {
            uint32_t ah[2][4];
#pragma unroll
            for (int mt = 0; mt < 2; mt++) {
                uint32_t addr = base + (OFF_AH + a_row_off + mt * 16 * 40 + kk) * 2;
                ldsm4(ah[mt][0], ah[mt][1], ah[mt][2], ah[mt][3], addr);
            }
            uint32_t bh[8][2];
#pragma unroll
            for (int p = 0; p < 4; p++) {
                uint32_t addr = base + (OFF_BH + (b_row_i + p * 16) * 40 + kk + b_col_off) * 2;
                ldsm4(bh[2 * p][0], bh[2 * p][1], bh[2 * p + 1][0], bh[2 * p + 1][1], addr);
            }
#pragma unroll
            for (int mt = 0; mt < 2; mt++)
#pragma unroll
                for (int nt = 0; nt < 8; nt++)
                    mmah16(acc[mt][nt], ah[mt], bh[nt]);
        }
        __syncthreads();
        buf ^= 1;
    }

#pragma unroll
    for (int mt = 0; mt < 2; mt++) {
#pragma unroll
        for (int nt = 0; nt < 8; nt++) {
            int row = mBase + wm + mt * 16 + (lane >> 2);
            int col = nBase + wn + nt * 8 + 2 * (lane & 3);
            float b0 = bias[col], b1 = bias[col + 1];
            if (row < N_NODES) {
                __half2 h = __floats2half2_rn(acc[mt][nt][0] + b0, acc[mt][nt][1] + b1);
                *reinterpret_cast<__half2*>(&g_proph[(size_t)row * NBIG + col]) = h;
            }
            if (row + 8 < N_NODES) {
                __half2 h = __floats2half2_rn(acc[mt][nt][2] + b0, acc[mt][nt][3] + b1);
                *reinterpret_cast<__half2*>(&g_proph[(size_t)(row + 8) * NBIG + col]) = h;
            }
        }
    }
}

// ---------------- message: padded segments, ping-pong pipeline --------------
__device__ __forceinline__ void acc_rec(uint4 v, uint4 g, float4& a0, float4& a1) {
    float2 f, gg;
    f  = __half22float2(*reinterpret_cast<__half2*>(&v.x));
    gg = __half22float2(*reinterpret_cast<__half2*>(&g.x));
    a0.x += f.x * gg.x; a0.y += f.y * gg.y;
    f  = __half22float2(*reinterpret_cast<__half2*>(&v.y));
    gg = __half22float2(*reinterpret_cast<__half2*>(&g.y));
    a0.z += f.x * gg.x; a0.w += f.y * gg.y;
    f  = __half22float2(*reinterpret_cast<__half2*>(&v.z));
    gg = __half22float2(*reinterpret_cast<__half2*>(&g.z));
    a1.x += f.x * gg.x; a1.y += f.y * gg.y;
    f  = __half22float2(*reinterpret_cast<__half2*>(&v.w));
    gg = __half22float2(*reinterpret_cast<__half2*>(&g.w));
    a1.z += f.x * gg.x; a1.w += f.y * gg.y;
}

// Segment starts/lengths are multiples of 8 -> every LOAD4 base is 16B-aligned,
// so the 4 record indices come in as ONE uint4 load.
#define LOAD4(E, V, G) do {                                                     \
    uint4 _c = *reinterpret_cast<const uint4*>(&g_sorted[(E)]);                 \
    V[0] = __ldg(reinterpret_cast<const uint4*>(                                \
        g_proph + (size_t)(_c.x >> 12) * NBIG + ((_c.x >> 9) & 7) * DIM) + lane);\
    V[1] = __ldg(reinterpret_cast<const uint4*>(                                \
        g_proph + (size_t)(_c.y >> 12) * NBIG + ((_c.y >> 9) & 7) * DIM) + lane);\
    V[2] = __ldg(reinterpret_cast<const uint4*>(                                \
        g_proph + (size_t)(_c.z >> 12) * NBIG + ((_c.z >> 9) & 7) * DIM) + lane);\
    V[3] = __ldg(reinterpret_cast<const uint4*>(                                \
        g_proph + (size_t)(_c.w >> 12) * NBIG + ((_c.w >> 9) & 7) * DIM) + lane);\
    G[0] = __ldg(reinterpret_cast<const uint4*>(                                \
        g_gatingh + (size_t)(_c.x & 511) * DIM) + lane);                        \
    G[1] = __ldg(reinterpret_cast<const uint4*>(                                \
        g_gatingh + (size_t)(_c.y & 511) * DIM) + lane);                        \
    G[2] = __ldg(reinterpret_cast<const uint4*>(                                \
        g_gatingh + (size_t)(_c.z & 511) * DIM) + lane);                        \
    G[3] = __ldg(reinterpret_cast<const uint4*>(                                \
        g_gatingh + (size_t)(_c.w & 511) * DIM) + lane);                        \
} while (0)

#define CONS4(V, G) do {                                                        \
    acc_rec(V[0], G[0], a0, a1);                                                \
    acc_rec(V[1], G[1], a0, a1);                                                \
    acc_rec(V[2], G[2], a0, a1);                                                \
    acc_rec(V[3], G[3], a0, a1);                                                \
} while (0)

__global__ __launch_bounds__(256)
void message_kernel(float* __restrict__ out) {
    int t    = (blockIdx.x * blockDim.x + threadIdx.x) >> 5;
    int lane = threadIdx.x & 31;
    if (t >= N_NODES) return;

    const int s0 = g_off[t];
    const int s1 = g_off[t + 1];    // padded end (multiple of 8 length)

    float4 a0 = make_float4(0.f, 0.f, 0.f, 0.f);
    float4 a1 = make_float4(0.f, 0.f, 0.f, 0.f);

    if (s0 < s1) {
        uint4 vA[4], gA[4], vB[4], gB[4];
        LOAD4(s0, vA, gA);
        int e = s0;
        for (; e + 8 < s1; e += 8) {
            LOAD4(e + 4, vB, gB);
            CONS4(vA, gA);
            LOAD4(e + 8, vA, gA);
            CONS4(vB, gB);
        }
        LOAD4(e + 4, vB, gB);
        CONS4(vA, gA);
        CONS4(vB, gB);
    }

    int deg = g_cnt[t];             // true degree
    float div = ((deg == 0) ? 1.0f : (float)deg) + 1e-8f;
    float s = 1.0f / div;
    a0.x *= s; a0.y *= s; a0.z *= s; a0.w *= s;
    a1.x *= s; a1.y *= s; a1.z *= s; a1.w *= s;

    float4* dst = reinterpret_cast<float4*>(out + (size_t)t * DIM) + lane * 2;
    dst[0] = a0;
    dst[1] = a1;
}

// ---------------- launch: two-stream fork/join; gemm submitted EARLY ---------
// Submission order is a pure permutation (same stream/event dependencies) so
// execution is identical — but it moves gemm_kernel into ncu's -s window.
extern "C" void kernel_launch(void* const* d_in, const int* in_sizes, int n_in,
                              void* d_out, int out_size) {
    const float* node_states = (const float*)d_in[0];
    const float* W    = (const float*)d_in[1];
    const float* b    = (const float*)d_in[2];
    const float* Wp   = (const float*)d_in[3];
    const float* bp   = (const float*)d_in[4];
    const int*   edges = (const int*)d_in[5];
    const int*   posl  = (const int*)d_in[6];
    float* out = (float*)d_out;

    static cudaStream_t sB = nullptr;
    static cudaEvent_t  evFork = nullptr, evJoin = nullptr;
    if (!sB) {
        cudaStreamCreateWithFlags(&sB, cudaStreamNonBlocking);
        cudaEventCreateWithFlags(&evFork, cudaEventDisableTiming);
        cudaEventCreateWithFlags(&evJoin, cudaEventDisableTiming);
        cudaFuncSetAttribute(gemm_kernel,
                             cudaFuncAttributeMaxDynamicSharedMemorySize,
                             SMEM_GEMM_BYTES);
    }

    cudaEventRecord(evFork, 0);
    cudaStreamWaitEvent(sB, evFork, 0);

    // launch 1 (stream 0)
    convert_kernel<<<((N_NODES + NBIG) * DIM + 255) / 256, 256>>>(node_states, W);
    // launches 2-3 (stream sB)
    gating_kernel<<<POS_TAB, 256, 0, sB>>>(Wp, bp);
    hist_kernel<<<(TOTAL_EDGES + 255) / 256, 256, 0, sB>>>(edges);
    // launch 4 (stream 0) — the GEMM, early in submission order for profiling
    dim3 gg(NBIG / 128, N_PAD / 128);
    gemm_kernel<<<gg, 256, SMEM_GEMM_BYTES>>>(b);
    // launches 5-9 (stream sB)
    scan1_kernel<<<N_SBLK, SCAN_BLK, 0, sB>>>();
    scan2_kernel<<<1, 128, 0, sB>>>();
    scan3_kernel<<<N_SBLK, SCAN_BLK, 0, sB>>>();
    place_kernel<<<(TOTAL_EDGES + 255) / 256, 256, 0, sB>>>(edges, posl);
    fill_kernel<<<(N_NODES + 255) / 256, 256, 0, sB>>>();
    cudaEventRecord(evJoin, sB);

    // launch 10 (stream 0)
    cudaStreamWaitEvent(0, evJoin, 0);
    message_kernel<<<(N_NODES * 32 + 255) / 256, 256>>>(out);
}